// round 16
// baseline (speedup 1.0000x reference)
#include <cuda_runtime.h>
#include <cuda_bf16.h>
#include <cuda_pipeline.h>
#include <mma.h>
#include <cstdint>

using namespace nvcuda;

#define NAG  8192
#define OBSD 64
#define HID  128
#define ACTD 16
#define NITEMS 1024        // 128 M-tiles x 8 k-quarters
#define GRID2  148         // persistent CTAs = SM count
#define NCHI   8           // chunks per item (1024 k / 128)

// Scratch (device globals: no allocations allowed)
__device__ float          g_h   [NAG * HID];       // fp32 encoder output
__device__ __nv_bfloat16  g_hb  [NAG * HID];       // bf16 h (row-major)
__device__ float          g_msgp[8][NAG * HID];    // per-k-quarter partial sums
__device__ int            g_degp[8][NAG];          // per-k-quarter degrees

// ---------------------------------------------------------------------------
// K1: h = tanh(obs @ W1 + b1) -> g_h (fp32) + g_hb (bf16).
// R16: persistent 148 CTAs — W1 loaded into smem ONCE per CTA (was 1024x).
// ---------------------------------------------------------------------------
__global__ void __launch_bounds__(256) k1_encoder(const float* __restrict__ obs,
                                                  const float* __restrict__ W1,
                                                  const float* __restrict__ b1) {
    __shared__ __align__(16) float sW1[OBSD * HID];   // 32 KB
    __shared__ float sObs[8][OBSD];
    const int t = threadIdx.x;

    #pragma unroll
    for (int i = 0; i < (OBSD * HID) / 256; ++i)
        sW1[i * 256 + t] = W1[i * 256 + t];

    const int w = t >> 5, l = t & 31;
    const float4 bb = *reinterpret_cast<const float4*>(&b1[l * 4]);
    __syncthreads();

    for (int blk = blockIdx.x; blk < NAG / 8; blk += GRID2) {
        const int a0 = blk * 8;
        #pragma unroll
        for (int i = 0; i < 2; ++i) {
            int idx = i * 256 + t;
            sObs[idx >> 6][idx & 63] = obs[(size_t)(a0 + (idx >> 6)) * OBSD + (idx & 63)];
        }
        __syncthreads();

        float acc0 = 0.f, acc1 = 0.f, acc2 = 0.f, acc3 = 0.f;
        #pragma unroll 8
        for (int k = 0; k < OBSD; ++k) {
            float o = sObs[w][k];
            float4 wv = *reinterpret_cast<const float4*>(&sW1[k * HID + l * 4]);
            acc0 = fmaf(o, wv.x, acc0);
            acc1 = fmaf(o, wv.y, acc1);
            acc2 = fmaf(o, wv.z, acc2);
            acc3 = fmaf(o, wv.w, acc3);
        }
        float h0 = tanhf(acc0 + bb.x);
        float h1 = tanhf(acc1 + bb.y);
        float h2 = tanhf(acc2 + bb.z);
        float h3 = tanhf(acc3 + bb.w);

        const size_t off = (size_t)(a0 + w) * HID + l * 4;
        float4 hv; hv.x = h0; hv.y = h1; hv.z = h2; hv.w = h3;
        *reinterpret_cast<float4*>(&g_h[off]) = hv;
        __nv_bfloat162 p0 = __floats2bfloat162_rn(h0, h1);
        __nv_bfloat162 p1 = __floats2bfloat162_rn(h2, h3);
        *reinterpret_cast<__nv_bfloat162*>(&g_hb[off])     = p0;
        *reinterpret_cast<__nv_bfloat162*>(&g_hb[off + 2]) = p1;
        __syncthreads();                   // sObs reads done before next load
    }
}

// no-op spacers: shift ncu's captured launch (-s 5 -c 1) onto k2_msg
__global__ void knop() {}

// ---------------------------------------------------------------------------
// K2: bf16 WMMA msg partials; persistent 148 CTAs x 512 threads.
// R16: chunk 128k (NCHI=8) — half the barriers/convert phases per item.
// Ring-3 B stages (128 k-rows x 272B); A conv [64][272B] x2; convert split
// into two halves interleaved between the two MMA ks-passes (A prefetch
// stays 8 ints/thread -> no reg growth). Warp = wm(2) x wn(2x64c) x kh(4),
// ks = kh*2+s. __ldcs A loads. ONE barrier per chunk. Epilogue: 4 kh tiles
// merged via smem overlay (R15).
// ---------------------------------------------------------------------------
__device__ __forceinline__ unsigned pack2i(int a, int b) {
    return (a ? 0x3F80u : 0u) | (b ? 0x3F800000u : 0u);   // two bf16 {0,1}
}

#define K2_BS    34816                     // B stage: 128 x 272 B
#define K2_RING  (3 * K2_BS)               // 104448
#define K2_ABF   17408                     // converted A: 64 x 272 B
#define K2_TILE  33792                     // fp32 [64][132] epilogue tile
#define K2_SMEM  (K2_RING + 2 * K2_ABF)    // 139264 (>= 4*K2_TILE = 135168)

__global__ void __launch_bounds__(512, 1) k2_msg(const int* __restrict__ adj) {
    extern __shared__ __align__(16) char sm2[];
    __shared__ int sDeg[64];

    const int t    = threadIdx.x;
    const int wid  = t >> 5;
    const int irow = t >> 3;       // 0..63 (A row)
    const int ig8  = t & 7;        // 16-int group within 128-int row
    const int krow = t >> 2;       // 0..127 (B k-row)
    const int q4   = t & 3;        // 64B quarter of B row
    const int wm   = wid & 1;          // M block (32 rows)
    const int wn   = (wid >> 1) & 1;   // N block (64 cols)
    const int kh   = wid >> 2;         // ks pair (0..3); ks = kh*2+s

    for (int item = blockIdx.x; item < NITEMS; item += GRID2) {
        const int mt = item & 127;
        const int kq = item >> 7;
        const int m0 = mt * 64;
        const int k0 = kq * 1024;

        const int*  gA = adj + (size_t)(m0 + irow) * NAG + k0 + ig8 * 16;
        const char* gB = reinterpret_cast<const char*>(g_hb) +
                         (size_t)(k0 + krow) * (HID * 2) + q4 * 64;

        if (t < 64) sDeg[t] = 0;
        int cnt = 0;

        auto issue_stage = [&](int c) {    // B: 128 k-rows x 256B per chunk
            char* st = sm2 + (c % 3) * K2_BS;
            const char* gb = gB + (size_t)c * 128 * 256;
            #pragma unroll
            for (int q = 0; q < 4; ++q)
                __pipeline_memcpy_async(st + krow * 272 + q4 * 64 + q * 16,
                                        gb + q * 16, 16);
        };
        auto convert_half = [&](int cc, int half, int4 A0, int4 A1) {
            char* sAbf = sm2 + K2_RING + (cc & 1) * K2_ABF;
            cnt += A0.x + A0.y + A0.z + A0.w + A1.x + A1.y + A1.z + A1.w;
            uint4 w;
            w.x = pack2i(A0.x, A0.y); w.y = pack2i(A0.z, A0.w);
            w.z = pack2i(A1.x, A1.y); w.w = pack2i(A1.z, A1.w);
            *reinterpret_cast<uint4*>(sAbf + irow * 272 + ig8 * 32 + half * 16) = w;
        };

        // prologue: convert chunk 0 fully (both halves), prefetch (1, half0)
        {
            const int4* p0 = reinterpret_cast<const int4*>(gA);
            int4 h0a = __ldcs(p0), h0b = __ldcs(p0 + 1);
            int4 h1a = __ldcs(p0 + 2), h1b = __ldcs(p0 + 3);
            issue_stage(0); __pipeline_commit();
            issue_stage(1); __pipeline_commit();
            __pipeline_wait_prior(1);      // B stage 0 landed (own copies)
            convert_half(0, 0, h0a, h0b);
            convert_half(0, 1, h1a, h1b);
        }
        int4 ava, avb;                     // prefetch buffer: 8 ints
        {
            const int4* p = reinterpret_cast<const int4*>(gA + 128);
            ava = __ldcs(p); avb = __ldcs(p + 1);
        }

        wmma::fragment<wmma::accumulator, 16, 16, 16, float> acc[2][4];
        #pragma unroll
        for (int i = 0; i < 2; ++i)
            #pragma unroll
            for (int j = 0; j < 4; ++j)
                wmma::fill_fragment(acc[i][j], 0.0f);
        __syncthreads();                   // Abf[0] + B stage 0 visible

        for (int c = 0; c < NCHI; ++c) {
            if (c + 2 < NCHI) issue_stage(c + 2);
            __pipeline_commit();
            __pipeline_wait_prior(1);      // B stage c+1 landed (own copies)

            const __nv_bfloat16* A =
                reinterpret_cast<const __nv_bfloat16*>(sm2 + K2_RING + (c & 1) * K2_ABF);
            const __nv_bfloat16* B =
                reinterpret_cast<const __nv_bfloat16*>(sm2 + (c % 3) * K2_BS);

            if (c + 1 < NCHI) {
                convert_half(c + 1, 0, ava, avb);
                const int4* p = reinterpret_cast<const int4*>(gA + (c + 1) * 128 + 8);
                ava = __ldcs(p); avb = __ldcs(p + 1);
            }
            #pragma unroll
            for (int s = 0; s < 2; ++s) {
                if (s == 1 && c + 1 < NCHI) {
                    convert_half(c + 1, 1, ava, avb);
                    if (c + 2 < NCHI) {
                        const int4* p = reinterpret_cast<const int4*>(gA + (c + 2) * 128);
                        ava = __ldcs(p); avb = __ldcs(p + 1);
                    }
                }
                const int ks = kh * 2 + s;
                wmma::fragment<wmma::matrix_a, 16, 16, 16, __nv_bfloat16, wmma::row_major> af[2];
                wmma::fragment<wmma::matrix_b, 16, 16, 16, __nv_bfloat16, wmma::row_major> bf[4];
                #pragma unroll
                for (int i = 0; i < 2; ++i)
                    wmma::load_matrix_sync(af[i], &A[(wm * 32 + i * 16) * 136 + ks * 16], 136);
                #pragma unroll
                for (int j = 0; j < 4; ++j)
                    wmma::load_matrix_sync(bf[j], &B[(ks * 16) * 136 + wn * 64 + j * 16], 136);
                #pragma unroll
                for (int i = 0; i < 2; ++i)
                    #pragma unroll
                    for (int j = 0; j < 4; ++j)
                        wmma::mma_sync(acc[i][j], af[i], bf[j], acc[i][j]);
            }
            __syncthreads();               // Abf[(c+1)&1] + B slot reuse safe
        }

        atomicAdd(&sDeg[irow], cnt);

        // 4 kh partial tiles in smem overlay (ring dead after final barrier)
        float* dstAcc = reinterpret_cast<float*>(sm2 + kh * K2_TILE);
        #pragma unroll
        for (int i = 0; i < 2; ++i)
            #pragma unroll
            for (int j = 0; j < 4; ++j)
                wmma::store_matrix_sync(&dstAcc[(wm * 32 + i * 16) * 132 + wn * 64 + j * 16],
                                        acc[i][j], 132, wmma::mem_row_major);
        __syncthreads();

        // merge 4 kh tiles -> g_msgp[kq] (8192 floats; disjoint rows per item)
        const float* s0 = reinterpret_cast<const float*>(sm2);
        const float* s1 = reinterpret_cast<const float*>(sm2 + K2_TILE);
        const float* s2 = reinterpret_cast<const float*>(sm2 + 2 * K2_TILE);
        const float* s3 = reinterpret_cast<const float*>(sm2 + 3 * K2_TILE);
        float* dst = g_msgp[kq];
        #pragma unroll
        for (int i = 0; i < 16; ++i) {
            int idx = i * 512 + t;
            int row = idx >> 7, col = idx & 127;
            int o = row * 132 + col;
            dst[(size_t)(m0 + row) * HID + col] = s0[o] + s1[o] + s2[o] + s3[o];
        }
        if (t < 64) g_degp[kq][m0 + t] = sDeg[t];
        __syncthreads();                   // overlay/sDeg reads done before next item
    }
}

// ---------------------------------------------------------------------------
// K3: merge 8 partials -> msg; hid = tanh([h,msg]@W2+b2); out = hid@W3+b3.
// ---------------------------------------------------------------------------
#define K3_SMEM (4 * (32768 + 16448 + 2048 + 128 + 16 + 64))   // 205,888 B

__global__ void __launch_bounds__(256, 1) k3_actor(float* __restrict__ out,
        const float* __restrict__ W2, const float* __restrict__ b2,
        const float* __restrict__ W3, const float* __restrict__ b3) {
    extern __shared__ __align__(16) float sm[];
    float* sW2 = sm;                   // [256][128]
    float* sC  = sm + 32768;           // [64][257]; reused as hid [64][129]
    float* sW3 = sC + 16448;           // [128][16]
    float* sb2 = sW3 + 2048;
    float* sb3 = sb2 + 128;
    float* sInv = sb3 + 16;            // [64] 1/deg

    const int t  = threadIdx.x;
    const int a0 = blockIdx.x * 64;

    #pragma unroll 4
    for (int i = 0; i < 128; ++i) sW2[i * 256 + t] = W2[i * 256 + t];
    #pragma unroll
    for (int i = 0; i < 8; ++i)   sW3[i * 256 + t] = W3[i * 256 + t];
    if (t < 128) sb2[t] = b2[t];
    if (t < 16)  sb3[t] = b3[t];
    if (t < 64) {
        int d = 0;
        #pragma unroll
        for (int p = 0; p < 8; ++p) d += g_degp[p][a0 + t];
        sInv[t] = 1.0f / (float)max(d, 1);
    }
    __syncthreads();
    #pragma unroll 4
    for (int i = 0; i < 32; ++i) {
        int idx = i * 256 + t;
        int a = idx >> 7, k = idx & 127;
        size_t o = (size_t)(a0 + a) * HID + k;
        sC[a * 257 + k] = g_h[o];
        float s = 0.f;
        #pragma unroll
        for (int p = 0; p < 8; ++p) s += g_msgp[p][o];
        sC[a * 257 + 128 + k] = s * sInv[a];
    }
    __syncthreads();

    const int ar = t >> 4;
    const int cc = t & 15;
    float acc[4][8];
    #pragma unroll
    for (int j = 0; j < 4; ++j)
        #pragma unroll
        for (int i = 0; i < 8; ++i) acc[j][i] = 0.f;

    #pragma unroll 2
    for (int k = 0; k < 2 * HID; ++k) {
        float4 w0 = *reinterpret_cast<const float4*>(&sW2[k * 128 + cc * 8]);
        float4 w1 = *reinterpret_cast<const float4*>(&sW2[k * 128 + cc * 8 + 4]);
        #pragma unroll
        for (int j = 0; j < 4; ++j) {
            float cv = sC[(ar * 4 + j) * 257 + k];
            acc[j][0] = fmaf(cv, w0.x, acc[j][0]);
            acc[j][1] = fmaf(cv, w0.y, acc[j][1]);
            acc[j][2] = fmaf(cv, w0.z, acc[j][2]);
            acc[j][3] = fmaf(cv, w0.w, acc[j][3]);
            acc[j][4] = fmaf(cv, w1.x, acc[j][4]);
            acc[j][5] = fmaf(cv, w1.y, acc[j][5]);
            acc[j][6] = fmaf(cv, w1.z, acc[j][6]);
            acc[j][7] = fmaf(cv, w1.w, acc[j][7]);
        }
    }
    __syncthreads();
    float* sH = sC;                       // [64][129]
    #pragma unroll
    for (int j = 0; j < 4; ++j) {
        int a = ar * 4 + j;
        #pragma unroll
        for (int i = 0; i < 8; ++i) {
            int ccol = cc * 8 + i;
            sH[a * 129 + ccol] = tanhf(acc[j][i] + sb2[ccol]);
        }
    }
    __syncthreads();

    const int a  = t >> 2;
    const int cq = t & 3;
    float4 lg; lg.x = 0.f; lg.y = 0.f; lg.z = 0.f; lg.w = 0.f;
    #pragma unroll 8
    for (int k = 0; k < HID; ++k) {
        float hv  = sH[a * 129 + k];
        float4 w3 = *reinterpret_cast<const float4*>(&sW3[k * 16 + cq * 4]);
        lg.x = fmaf(hv, w3.x, lg.x);
        lg.y = fmaf(hv, w3.y, lg.y);
        lg.z = fmaf(hv, w3.z, lg.z);
        lg.w = fmaf(hv, w3.w, lg.w);
    }
    lg.x += sb3[cq * 4 + 0];
    lg.y += sb3[cq * 4 + 1];
    lg.z += sb3[cq * 4 + 2];
    lg.w += sb3[cq * 4 + 3];
    *reinterpret_cast<float4*>(&out[(size_t)(a0 + a) * ACTD + cq * 4]) = lg;
}

// ---------------------------------------------------------------------------
extern "C" void kernel_launch(void* const* d_in, const int* in_sizes, int n_in,
                              void* d_out, int out_size) {
    const float* obs = (const float*)d_in[0];
    const int*   adj = (const int*)  d_in[1];
    const float* W1  = (const float*)d_in[2];
    const float* b1  = (const float*)d_in[3];
    const float* W2  = (const float*)d_in[4];
    const float* b2  = (const float*)d_in[5];
    const float* W3  = (const float*)d_in[6];
    const float* b3  = (const float*)d_in[7];
    float* out = (float*)d_out;

    cudaFuncSetAttribute(k2_msg,   cudaFuncAttributeMaxDynamicSharedMemorySize, K2_SMEM);
    cudaFuncSetAttribute(k3_actor, cudaFuncAttributeMaxDynamicSharedMemorySize, K3_SMEM);

    k1_encoder<<<GRID2, 256>>>(obs, W1, b1);
    knop<<<1, 32>>>();                 // spacers: land ncu capture on k2_msg
    knop<<<1, 32>>>();
    k2_msg    <<<GRID2, 512, K2_SMEM>>>(adj);
    k3_actor  <<<NAG / 64, 256, K3_SMEM>>>(out, W2, b2, W3, b3);
}

// round 17
// speedup vs baseline: 1.1713x; 1.1713x over previous
#include <cuda_runtime.h>
#include <cuda_bf16.h>
#include <cuda_pipeline.h>
#include <mma.h>
#include <cstdint>

using namespace nvcuda;

#define NAG  8192
#define OBSD 64
#define HID  128
#define ACTD 16
#define NITEMS 1024        // 128 M-tiles x 8 k-quarters
#define GRID2  148         // persistent CTAs = SM count
#define NCHI   16          // chunks per item (1024 k / 64)

// Scratch (device globals: no allocations allowed)
__device__ float          g_h   [NAG * HID];       // fp32 encoder output
__device__ __nv_bfloat16  g_hb  [NAG * HID];       // bf16 h (row-major)
__device__ float          g_msgp[8][NAG * HID];    // per-k-quarter partial sums
__device__ int            g_degp[8][NAG];          // per-k-quarter degrees

// ---------------------------------------------------------------------------
// K1: h = tanh(obs @ W1 + b1) -> g_h (fp32) + g_hb (bf16).  (R15 version)
// ---------------------------------------------------------------------------
__global__ void __launch_bounds__(256) k1_encoder(const float* __restrict__ obs,
                                                  const float* __restrict__ W1,
                                                  const float* __restrict__ b1) {
    __shared__ __align__(16) float sW1[OBSD * HID];   // 32 KB
    __shared__ float sObs[8][OBSD];
    const int t  = threadIdx.x;
    const int a0 = blockIdx.x * 8;

    #pragma unroll
    for (int i = 0; i < (OBSD * HID) / 256; ++i)
        sW1[i * 256 + t] = W1[i * 256 + t];
    #pragma unroll
    for (int i = 0; i < 2; ++i) {
        int idx = i * 256 + t;
        sObs[idx >> 6][idx & 63] = obs[(size_t)(a0 + (idx >> 6)) * OBSD + (idx & 63)];
    }
    __syncthreads();

    const int w = t >> 5, l = t & 31;
    const int agent = a0 + w;
    float acc0 = 0.f, acc1 = 0.f, acc2 = 0.f, acc3 = 0.f;
    #pragma unroll 8
    for (int k = 0; k < OBSD; ++k) {
        float o = sObs[w][k];
        float4 wv = *reinterpret_cast<const float4*>(&sW1[k * HID + l * 4]);
        acc0 = fmaf(o, wv.x, acc0);
        acc1 = fmaf(o, wv.y, acc1);
        acc2 = fmaf(o, wv.z, acc2);
        acc3 = fmaf(o, wv.w, acc3);
    }
    float4 bb = *reinterpret_cast<const float4*>(&b1[l * 4]);
    float h0 = tanhf(acc0 + bb.x);
    float h1 = tanhf(acc1 + bb.y);
    float h2 = tanhf(acc2 + bb.z);
    float h3 = tanhf(acc3 + bb.w);

    const size_t off = (size_t)agent * HID + l * 4;
    float4 hv; hv.x = h0; hv.y = h1; hv.z = h2; hv.w = h3;
    *reinterpret_cast<float4*>(&g_h[off]) = hv;
    __nv_bfloat162 p0 = __floats2bfloat162_rn(h0, h1);
    __nv_bfloat162 p1 = __floats2bfloat162_rn(h2, h3);
    *reinterpret_cast<__nv_bfloat162*>(&g_hb[off])     = p0;
    *reinterpret_cast<__nv_bfloat162*>(&g_hb[off + 2]) = p1;
}

// no-op spacers: shift ncu's captured launch (-s 5 -c 1) onto k2_msg
__global__ void knop() {}

// ---------------------------------------------------------------------------
// K2: bf16 WMMA msg partials; persistent 148 CTAs x 512 threads (R15 core).
// Warp map wm(2) x wn(2) x kh(4): each warp 32Mx64N for ONE ks; __ldcs A;
// A path LDG->regs->convert->STS; B-only ring-4 cp.async; ONE barrier/chunk;
// epilogue merges 4 kh tiles (R17: float4-vectorized merge).
// ---------------------------------------------------------------------------
__device__ __forceinline__ unsigned pack2i(int a, int b) {
    return (a ? 0x3F80u : 0u) | (b ? 0x3F800000u : 0u);   // two bf16 {0,1}
}

#define K2_BS    17408                     // B bf16 stage: 64 x 272 B
#define K2_RING  (4 * K2_BS)               // 69632
#define K2_ABF   9216                      // converted A: 64 x 144 B
#define K2_TILE  33792                     // fp32 [64][132] epilogue tile
#define K2_SMEM  (4 * K2_TILE)             // 135168 (> ring+2*ABF = 88064)

__global__ void __launch_bounds__(512, 1) k2_msg(const int* __restrict__ adj) {
    extern __shared__ __align__(16) char sm2[];
    __shared__ int sDeg[64];

    const int t    = threadIdx.x;
    const int wid  = t >> 5;
    const int irow = t >> 3;       // 0..63 (A row & B k-row)
    const int ig8  = t & 7;        // 32B group within row
    const int wm   = wid & 1;          // M block (32 rows)
    const int wn   = (wid >> 1) & 1;   // N block (64 cols)
    const int kh   = wid >> 2;         // ks (0..3), one 16k slice per warp

    for (int item = blockIdx.x; item < NITEMS; item += GRID2) {
        const int mt = item & 127;
        const int kq = item >> 7;
        const int m0 = mt * 64;
        const int k0 = kq * 1024;

        const int*  gA = adj + (size_t)(m0 + irow) * NAG + k0 + ig8 * 8;
        const char* gB = reinterpret_cast<const char*>(g_hb) +
                         (size_t)(k0 + irow) * (HID * 2) + ig8 * 32;

        if (t < 64) sDeg[t] = 0;
        int cnt = 0;

        wmma::fragment<wmma::accumulator, 16, 16, 16, float> acc[2][4];
        #pragma unroll
        for (int i = 0; i < 2; ++i)
            #pragma unroll
            for (int j = 0; j < 4; ++j)
                wmma::fill_fragment(acc[i][j], 0.0f);

        auto issue_stage = [&](int c) {    // B only
            char* st = sm2 + (c & 3) * K2_BS;
            const char* gb = gB + (size_t)c * 64 * 256;     // 64 k-rows x 256B
            #pragma unroll
            for (int q = 0; q < 2; ++q)
                __pipeline_memcpy_async(st + irow * 272 + ig8 * 32 + q * 16,
                                        gb + q * 16, 16);
        };

        // A register buffer: this thread's 8 int32 of the convert chunk
        int4 a0v, a1v;
        auto ldg_a = [&](int c) {
            const int4* p = reinterpret_cast<const int4*>(gA + c * 64);
            a0v = __ldcs(p); a1v = __ldcs(p + 1);           // stream-once
        };
        auto do_convert = [&](int cc) {    // regs -> bf16 STS; counts degree
            char* sAbf = sm2 + K2_RING + (cc & 1) * K2_ABF;
            cnt += a0v.x + a0v.y + a0v.z + a0v.w + a1v.x + a1v.y + a1v.z + a1v.w;
            uint4 w;
            w.x = pack2i(a0v.x, a0v.y); w.y = pack2i(a0v.z, a0v.w);
            w.z = pack2i(a1v.x, a1v.y); w.w = pack2i(a1v.z, a1v.w);
            *reinterpret_cast<uint4*>(sAbf + irow * 144 + ig8 * 16) = w;
        };

        ldg_a(0);
        issue_stage(0); __pipeline_commit();
        issue_stage(1); __pipeline_commit();
        issue_stage(2); __pipeline_commit();
        __pipeline_wait_prior(2);          // B stage 0 landed (own copies)
        do_convert(0);
        ldg_a(1);                          // in flight across compute(0)
        __syncthreads();                   // Abf[0] + B stage 0 visible

        for (int c = 0; c < NCHI; ++c) {
            if (c + 3 < NCHI) issue_stage(c + 3);
            __pipeline_commit();
            __pipeline_wait_prior(2);      // B stage c+1 landed (own copies)
            if (c + 1 < NCHI) {
                do_convert(c + 1);         // regs loaded at iter c-1
                if (c + 2 < NCHI) ldg_a(c + 2);
            }

            const __nv_bfloat16* A =
                reinterpret_cast<const __nv_bfloat16*>(sm2 + K2_RING + (c & 1) * K2_ABF);
            const __nv_bfloat16* B =
                reinterpret_cast<const __nv_bfloat16*>(sm2 + (c & 3) * K2_BS);
            {
                const int ks = kh;         // one 16k slice per warp
                wmma::fragment<wmma::matrix_a, 16, 16, 16, __nv_bfloat16, wmma::row_major> af[2];
                wmma::fragment<wmma::matrix_b, 16, 16, 16, __nv_bfloat16, wmma::row_major> bf[4];
                #pragma unroll
                for (int i = 0; i < 2; ++i)
                    wmma::load_matrix_sync(af[i], &A[(wm * 32 + i * 16) * 72 + ks * 16], 72);
                #pragma unroll
                for (int j = 0; j < 4; ++j)
                    wmma::load_matrix_sync(bf[j], &B[(ks * 16) * 136 + wn * 64 + j * 16], 136);
                #pragma unroll
                for (int i = 0; i < 2; ++i)
                    #pragma unroll
                    for (int j = 0; j < 4; ++j)
                        wmma::mma_sync(acc[i][j], af[i], bf[j], acc[i][j]);
            }
            __syncthreads();               // Abf[(c+1)&1] + B stage reuse safe
        }

        atomicAdd(&sDeg[irow], cnt);

        // 4 kh partial tiles in smem overlay (after final barrier: ring dead)
        float* dstAcc = reinterpret_cast<float*>(sm2 + kh * K2_TILE);
        #pragma unroll
        for (int i = 0; i < 2; ++i)
            #pragma unroll
            for (int j = 0; j < 4; ++j)
                wmma::store_matrix_sync(&dstAcc[(wm * 32 + i * 16) * 132 + wn * 64 + j * 16],
                                        acc[i][j], 132, wmma::mem_row_major);
        __syncthreads();

        // merge 4 kh tiles -> g_msgp[kq]  (float4: 2048 vec4, 4 per thread)
        const float4* s0 = reinterpret_cast<const float4*>(sm2);
        const float4* s1 = reinterpret_cast<const float4*>(sm2 + K2_TILE);
        const float4* s2 = reinterpret_cast<const float4*>(sm2 + 2 * K2_TILE);
        const float4* s3 = reinterpret_cast<const float4*>(sm2 + 3 * K2_TILE);
        float4* dst = reinterpret_cast<float4*>(g_msgp[kq]);
        #pragma unroll
        for (int i = 0; i < 4; ++i) {
            int v   = i * 512 + t;         // 0..2047
            int row = v >> 5;              // 32 float4 per row
            int c4  = v & 31;
            int o   = row * 33 + c4;       // 132 floats = 33 float4
            float4 r0 = s0[o], r1 = s1[o], r2 = s2[o], r3 = s3[o];
            float4 m;
            m.x = r0.x + r1.x + r2.x + r3.x;
            m.y = r0.y + r1.y + r2.y + r3.y;
            m.z = r0.z + r1.z + r2.z + r3.z;
            m.w = r0.w + r1.w + r2.w + r3.w;
            dst[(size_t)(m0 + row) * 32 + c4] = m;
        }
        if (t < 64) g_degp[kq][m0 + t] = sDeg[t];
        __syncthreads();                   // overlay/sDeg reads done before next item
    }
}

// ---------------------------------------------------------------------------
// K3: merge 8 partials -> msg; hid = tanh([h,msg]@W2+b2); out = hid@W3+b3.
// R17: float4-vectorized partial merge.
// ---------------------------------------------------------------------------
#define K3_SMEM (4 * (32768 + 16448 + 2048 + 128 + 16 + 64))   // 205,888 B

__global__ void __launch_bounds__(256, 1) k3_actor(float* __restrict__ out,
        const float* __restrict__ W2, const float* __restrict__ b2,
        const float* __restrict__ W3, const float* __restrict__ b3) {
    extern __shared__ __align__(16) float sm[];
    float* sW2 = sm;                   // [256][128]
    float* sC  = sm + 32768;           // [64][257]; reused as hid [64][129]
    float* sW3 = sC + 16448;           // [128][16]
    float* sb2 = sW3 + 2048;
    float* sb3 = sb2 + 128;
    float* sInv = sb3 + 16;            // [64] 1/deg

    const int t  = threadIdx.x;
    const int a0 = blockIdx.x * 64;

    #pragma unroll 4
    for (int i = 0; i < 128; ++i) sW2[i * 256 + t] = W2[i * 256 + t];
    #pragma unroll
    for (int i = 0; i < 8; ++i)   sW3[i * 256 + t] = W3[i * 256 + t];
    if (t < 128) sb2[t] = b2[t];
    if (t < 16)  sb3[t] = b3[t];
    if (t < 64) {
        int d = 0;
        #pragma unroll
        for (int p = 0; p < 8; ++p) d += g_degp[p][a0 + t];
        sInv[t] = 1.0f / (float)max(d, 1);
    }
    __syncthreads();
    // float4 merge: 64 agents x 32 float4 = 2048 vec4, 8 per thread
    #pragma unroll
    for (int i = 0; i < 8; ++i) {
        int v   = i * 256 + t;             // 0..2047
        int a   = v >> 5;
        int c4  = v & 31;
        size_t o = (size_t)(a0 + a) * 32 + c4;
        float4 hvec = reinterpret_cast<const float4*>(g_h)[o];
        float4 s = reinterpret_cast<const float4*>(g_msgp[0])[o];
        #pragma unroll
        for (int p = 1; p < 8; ++p) {
            float4 r = reinterpret_cast<const float4*>(g_msgp[p])[o];
            s.x += r.x; s.y += r.y; s.z += r.z; s.w += r.w;
        }
        float inv = sInv[a];
        int k = c4 * 4;
        sC[a * 257 + k]     = hvec.x;
        sC[a * 257 + k + 1] = hvec.y;
        sC[a * 257 + k + 2] = hvec.z;
        sC[a * 257 + k + 3] = hvec.w;
        sC[a * 257 + 128 + k]     = s.x * inv;
        sC[a * 257 + 128 + k + 1] = s.y * inv;
        sC[a * 257 + 128 + k + 2] = s.z * inv;
        sC[a * 257 + 128 + k + 3] = s.w * inv;
    }
    __syncthreads();

    const int ar = t >> 4;
    const int cc = t & 15;
    float acc[4][8];
    #pragma unroll
    for (int j = 0; j < 4; ++j)
        #pragma unroll
        for (int i = 0; i < 8; ++i) acc[j][i] = 0.f;

    #pragma unroll 2
    for (int k = 0; k < 2 * HID; ++k) {
        float4 w0 = *reinterpret_cast<const float4*>(&sW2[k * 128 + cc * 8]);
        float4 w1 = *reinterpret_cast<const float4*>(&sW2[k * 128 + cc * 8 + 4]);
        #pragma unroll
        for (int j = 0; j < 4; ++j) {
            float cv = sC[(ar * 4 + j) * 257 + k];
            acc[j][0] = fmaf(cv, w0.x, acc[j][0]);
            acc[j][1] = fmaf(cv, w0.y, acc[j][1]);
            acc[j][2] = fmaf(cv, w0.z, acc[j][2]);
            acc[j][3] = fmaf(cv, w0.w, acc[j][3]);
            acc[j][4] = fmaf(cv, w1.x, acc[j][4]);
            acc[j][5] = fmaf(cv, w1.y, acc[j][5]);
            acc[j][6] = fmaf(cv, w1.z, acc[j][6]);
            acc[j][7] = fmaf(cv, w1.w, acc[j][7]);
        }
    }
    __syncthreads();
    float* sH = sC;                       // [64][129]
    #pragma unroll
    for (int j = 0; j < 4; ++j) {
        int a = ar * 4 + j;
        #pragma unroll
        for (int i = 0; i < 8; ++i) {
            int ccol = cc * 8 + i;
            sH[a * 129 + ccol] = tanhf(acc[j][i] + sb2[ccol]);
        }
    }
    __syncthreads();

    const int a  = t >> 2;
    const int cq = t & 3;
    float4 lg; lg.x = 0.f; lg.y = 0.f; lg.z = 0.f; lg.w = 0.f;
    #pragma unroll 8
    for (int k = 0; k < HID; ++k) {
        float hv  = sH[a * 129 + k];
        float4 w3 = *reinterpret_cast<const float4*>(&sW3[k * 16 + cq * 4]);
        lg.x = fmaf(hv, w3.x, lg.x);
        lg.y = fmaf(hv, w3.y, lg.y);
        lg.z = fmaf(hv, w3.z, lg.z);
        lg.w = fmaf(hv, w3.w, lg.w);
    }
    lg.x += sb3[cq * 4 + 0];
    lg.y += sb3[cq * 4 + 1];
    lg.z += sb3[cq * 4 + 2];
    lg.w += sb3[cq * 4 + 3];
    *reinterpret_cast<float4*>(&out[(size_t)(a0 + a) * ACTD + cq * 4]) = lg;
}

// ---------------------------------------------------------------------------
extern "C" void kernel_launch(void* const* d_in, const int* in_sizes, int n_in,
                              void* d_out, int out_size) {
    const float* obs = (const float*)d_in[0];
    const int*   adj = (const int*)  d_in[1];
    const float* W1  = (const float*)d_in[2];
    const float* b1  = (const float*)d_in[3];
    const float* W2  = (const float*)d_in[4];
    const float* b2  = (const float*)d_in[5];
    const float* W3  = (const float*)d_in[6];
    const float* b3  = (const float*)d_in[7];
    float* out = (float*)d_out;

    cudaFuncSetAttribute(k2_msg,   cudaFuncAttributeMaxDynamicSharedMemorySize, K2_SMEM);
    cudaFuncSetAttribute(k3_actor, cudaFuncAttributeMaxDynamicSharedMemorySize, K3_SMEM);

    k1_encoder<<<NAG / 8, 256>>>(obs, W1, b1);
    knop<<<1, 32>>>();                 // spacers: land ncu capture on k2_msg
    knop<<<1, 32>>>();
    k2_msg    <<<GRID2, 512, K2_SMEM>>>(adj);
    k3_actor  <<<NAG / 64, 256, K3_SMEM>>>(out, W2, b2, W3, b3);
}